// round 2
// baseline (speedup 1.0000x reference)
#include <cuda_runtime.h>
#include <cuda_bf16.h>
#include <math.h>

// Problem constants
#define BB   256
#define SS   256
#define TT   48
#define HID  1024
#define EMB  256
#define NLAB 128

// ---------------------------------------------------------------------------
// Scratch (device globals; no allocation allowed)
// ---------------------------------------------------------------------------
__device__ float g_ctxp[(size_t)BB * SS * HID];        // 256 MB
__device__ float g_xcat[(size_t)BB * TT * (2 * EMB)];  // 24 MB
__device__ float g_gatesx[(size_t)BB * TT * 4 * HID];  // 201 MB
__device__ float g_gates[BB * 4 * HID];
__device__ float g_hcat[BB * 2 * HID];                 // [:, :HID]=weighted, [:, HID:]=h_lstm
__device__ float g_hbuf[BB * HID];                     // carried hidden (hidden_t)
__device__ float g_cbuf[BB * HID];                     // carried cell
__device__ float g_q[BB * HID];

// ---------------------------------------------------------------------------
// Generic tiled SGEMM:  C = A[M,K] * B[K,N] + bias[N] (+ add[M,N]) (opt tanh)
// Requires: M%BM==0, N%BN==0, K%BK==0, BM*BK==1024, BK*BN==1024, 256 threads.
// ---------------------------------------------------------------------------
template<int BM, int BN, int BK, int TM, int TN, bool DO_TANH>
__global__ void __launch_bounds__(256, 2)
sgemm_kernel(const float* __restrict__ A, int lda,
             const float* __restrict__ B, int ldb,
             const float* __restrict__ bias,
             const float* __restrict__ add, int ldadd,
             float* __restrict__ C, int ldc,
             int K)
{
    __shared__ float As[BK][BM];
    __shared__ float Bs[BK][BN];

    const int tid  = threadIdx.x;
    const int row0 = blockIdx.y * BM;
    const int col0 = blockIdx.x * BN;

    const int tx = tid % (BN / TN);
    const int ty = tid / (BN / TN);

    // A-tile load mapping (one float4 per thread)
    const int aflat = tid * 4;
    const int ar = aflat / BK;
    const int ac = aflat % BK;
    // B-tile load mapping (one float4 per thread)
    const int bflat = tid * 4;
    const int br = bflat / BN;
    const int bc = bflat % BN;

    float acc[TM][TN];
#pragma unroll
    for (int i = 0; i < TM; i++)
#pragma unroll
        for (int j = 0; j < TN; j++) acc[i][j] = 0.f;

    for (int k0 = 0; k0 < K; k0 += BK) {
        float4 av = *(const float4*)(A + (size_t)(row0 + ar) * lda + k0 + ac);
        As[ac + 0][ar] = av.x;
        As[ac + 1][ar] = av.y;
        As[ac + 2][ar] = av.z;
        As[ac + 3][ar] = av.w;
        float4 bv = *(const float4*)(B + (size_t)(k0 + br) * ldb + col0 + bc);
        *(float4*)&Bs[br][bc] = bv;
        __syncthreads();

#pragma unroll
        for (int kk = 0; kk < BK; kk++) {
            float af[TM], bf[TN];
#pragma unroll
            for (int i = 0; i < TM; i++) af[i] = As[kk][ty * TM + i];
#pragma unroll
            for (int j = 0; j < TN; j++) bf[j] = Bs[kk][tx * TN + j];
#pragma unroll
            for (int i = 0; i < TM; i++)
#pragma unroll
                for (int j = 0; j < TN; j++)
                    acc[i][j] = fmaf(af[i], bf[j], acc[i][j]);
        }
        __syncthreads();
    }

#pragma unroll
    for (int i = 0; i < TM; i++) {
        const int r = row0 + ty * TM + i;
#pragma unroll
        for (int j = 0; j < TN; j++) {
            const int c = col0 + tx * TN + j;
            float v = acc[i][j] + bias[c];
            if (add) v += add[(size_t)r * ldadd + c];
            if (DO_TANH) v = tanhf(v);
            C[(size_t)r * ldc + c] = v;
        }
    }
}

// ---------------------------------------------------------------------------
// xcat builder: xcat[b,t, 0:256] = (t==0 ? decoder_input[b] : emb[cur[b,t-1]])
//               xcat[b,t, 256:512] = emb[labels[b,t]]
// ---------------------------------------------------------------------------
__global__ void xcat_kernel(const float* __restrict__ dec,
                            const int* __restrict__ cur,
                            const int* __restrict__ lab,
                            const float* __restrict__ emb,
                            float* __restrict__ xcat)
{
    int idx = blockIdx.x * blockDim.x + threadIdx.x;
    if (idx >= BB * TT * 2 * EMB) return;
    int k  = idx & (2 * EMB - 1);
    int bt = idx >> 9;
    int t  = bt % TT;
    int b  = bt / TT;
    float v;
    if (k < EMB) {
        if (t == 0) v = dec[b * EMB + k];
        else        v = emb[cur[b * TT + (t - 1)] * EMB + k];
    } else {
        v = emb[lab[b * TT + t] * EMB + (k - EMB)];
    }
    xcat[idx] = v;
}

// ---------------------------------------------------------------------------
// LSTM cell pointwise: gates[B,4H] -> c update + h_lstm into hcat[:, HID:]
// ---------------------------------------------------------------------------
__global__ void lstm_kernel(const float* __restrict__ gates,
                            float* __restrict__ cbuf,
                            float* __restrict__ hcat)
{
    int idx = blockIdx.x * blockDim.x + threadIdx.x;
    if (idx >= BB * HID) return;
    int b = idx >> 10, j = idx & (HID - 1);
    const float* g = gates + (size_t)b * 4 * HID;
    float ig = g[j], fg = g[j + HID], gg = g[j + 2 * HID], og = g[j + 3 * HID];
    float si = 1.f / (1.f + expf(-ig));
    float sf = 1.f / (1.f + expf(-fg));
    float so = 1.f / (1.f + expf(-og));
    float cn = sf * cbuf[idx] + si * tanhf(gg);
    cbuf[idx] = cn;
    hcat[(size_t)b * 2 * HID + HID + j] = so * tanhf(cn);
}

// ---------------------------------------------------------------------------
// Fused Bahdanau attention with online softmax (single pass over ctx_proj).
// One block per batch row b.  512 threads (16 warps), chunk of 16 s-rows
// staged in smem; each warp computes e for one s, then all threads accumulate
// weighted sum with flash-style rescaling.  weighted -> hcat[:, :HID].
// ---------------------------------------------------------------------------
#define ATT_THREADS 512
#define ATT_CHUNK   16
#define ATT_SMEM_FLOATS (ATT_CHUNK * HID + HID + HID + ATT_CHUNK + ATT_CHUNK)

__global__ void __launch_bounds__(ATT_THREADS, 1)
att_kernel(const float* __restrict__ ctxp,
           const float* __restrict__ q,
           const float* __restrict__ Vw,
           float* __restrict__ hcat)
{
    extern __shared__ float sm[];
    float* chunk = sm;                       // 16*1024
    float* qs    = sm + ATT_CHUNK * HID;     // 1024
    float* Vs    = qs + HID;                 // 1024
    float* e_sm  = Vs + HID;                 // 16
    float* p_sm  = e_sm + ATT_CHUNK;         // 16

    const int b = blockIdx.x, tid = threadIdx.x;
    const int warp = tid >> 5, lane = tid & 31;

    for (int i = tid; i < HID; i += ATT_THREADS) {
        qs[i] = q[(size_t)b * HID + i];
        Vs[i] = Vw[i];
    }

    float m = -INFINITY, l = 0.f, acc0 = 0.f, acc1 = 0.f;
    const float* base = ctxp + (size_t)b * SS * HID;

    for (int s0 = 0; s0 < SS; s0 += ATT_CHUNK) {
        __syncthreads();  // chunk free (also covers q/V on first iter)
        const float4* src  = (const float4*)(base + (size_t)s0 * HID);
        float4*       dst4 = (float4*)chunk;
#pragma unroll
        for (int i = tid; i < ATT_CHUNK * HID / 4; i += ATT_THREADS) dst4[i] = src[i];
        __syncthreads();

        // e[s0+warp] = sum_h tanh(q[h] + ctx[h]) * V[h]
        {
            const float* row = chunk + warp * HID;
            float sum = 0.f;
#pragma unroll 8
            for (int i = lane; i < HID; i += 32)
                sum += tanhf(qs[i] + row[i]) * Vs[i];
#pragma unroll
            for (int off = 16; off; off >>= 1)
                sum += __shfl_xor_sync(0xffffffffu, sum, off);
            if (lane == 0) e_sm[warp] = sum;
        }
        __syncthreads();

        float mc = m;
#pragma unroll
        for (int s = 0; s < ATT_CHUNK; s++) mc = fmaxf(mc, e_sm[s]);
        float scale = expf(m - mc);
        if (tid < ATT_CHUNK) p_sm[tid] = expf(e_sm[tid] - mc);
        __syncthreads();

        float psum = 0.f, a0 = 0.f, a1 = 0.f;
#pragma unroll
        for (int s = 0; s < ATT_CHUNK; s++) {
            float p = p_sm[s];
            psum += p;
            a0 = fmaf(p, chunk[s * HID + tid], a0);
            a1 = fmaf(p, chunk[s * HID + tid + ATT_THREADS], a1);
        }
        l    = l * scale + psum;
        acc0 = acc0 * scale + a0;
        acc1 = acc1 * scale + a1;
        m    = mc;
    }

    float inv = 1.f / l;
    hcat[(size_t)b * 2 * HID + tid]               = acc0 * inv;
    hcat[(size_t)b * 2 * HID + tid + ATT_THREADS] = acc1 * inv;
}

// ---------------------------------------------------------------------------
// out = [hidden_t, weighted, x_t] @ W_out + b_out  (K=2304, N=128) + argmax.
// One block handles 4 batch rows to amortize W_out reads (L2 resident).
// ---------------------------------------------------------------------------
#define OUT_K (2 * HID + EMB)
__global__ void __launch_bounds__(NLAB)
out_kernel(const float* __restrict__ hbuf,
           const float* __restrict__ hcat,
           const float* __restrict__ xcat,
           const float* __restrict__ Wout,
           const float* __restrict__ bout,
           int t,
           float* __restrict__ outp,
           float* __restrict__ predp)
{
    __shared__ float arow[4][OUT_K];
    __shared__ float sv[NLAB];
    __shared__ int   si[NLAB];

    const int tid = threadIdx.x;            // 128
    const int b0  = blockIdx.x * 4;

    for (int idx = tid; idx < 4 * OUT_K; idx += NLAB) {
        int r = idx / OUT_K, k = idx % OUT_K;
        int b = b0 + r;
        float v;
        if (k < HID)            v = hbuf[(size_t)b * HID + k];
        else if (k < 2 * HID)   v = hcat[(size_t)b * 2 * HID + (k - HID)];
        else                    v = xcat[((size_t)b * TT + t) * (2 * EMB) + (k - 2 * HID)];
        arow[r][k] = v;
    }
    __syncthreads();

    float acc[4];
#pragma unroll
    for (int r = 0; r < 4; r++) acc[r] = bout[tid];

#pragma unroll 4
    for (int k = 0; k < OUT_K; k++) {
        float w = Wout[(size_t)k * NLAB + tid];
#pragma unroll
        for (int r = 0; r < 4; r++) acc[r] = fmaf(arow[r][k], w, acc[r]);
    }

#pragma unroll
    for (int r = 0; r < 4; r++)
        outp[((size_t)(b0 + r) * TT + t) * NLAB + tid] = acc[r];

    if (!predp) return;
    for (int r = 0; r < 4; r++) {
        __syncthreads();
        sv[tid] = acc[r];
        si[tid] = tid;
        __syncthreads();
        for (int off = NLAB / 2; off; off >>= 1) {
            if (tid < off) {
                float ov = sv[tid + off]; int oi = si[tid + off];
                if (ov > sv[tid] || (ov == sv[tid] && oi < si[tid])) {
                    sv[tid] = ov; si[tid] = oi;
                }
            }
            __syncthreads();
        }
        if (tid == 0) predp[(size_t)(b0 + r) * TT + t] = (float)si[0];
    }
}

// ---------------------------------------------------------------------------
// Launch
// ---------------------------------------------------------------------------
extern "C" void kernel_launch(void* const* d_in, const int* in_sizes, int n_in,
                              void* d_out, int out_size)
{
    (void)in_sizes; (void)n_in;
    // Input order per reference setup_inputs():
    const float* decoder_input = (const float*)d_in[2];
    const float* h0      = (const float*)d_in[3];
    const float* c0      = (const float*)d_in[4];
    const float* context = (const float*)d_in[5];
    const int*   cur     = (const int*)d_in[6];
    const int*   lab     = (const int*)d_in[7];
    const float* emb     = (const float*)d_in[8];
    const float* W_ih    = (const float*)d_in[9];
    const float* b_ih    = (const float*)d_in[10];
    const float* W_hh    = (const float*)d_in[11];
    const float* b_hh    = (const float*)d_in[12];
    const float* W_ho    = (const float*)d_in[13];
    const float* b_ho    = (const float*)d_in[14];
    const float* W_ain   = (const float*)d_in[15];
    const float* b_ain   = (const float*)d_in[16];
    const float* W_actx  = (const float*)d_in[17];
    const float* b_actx  = (const float*)d_in[18];
    const float* Vw      = (const float*)d_in[19];
    const float* W_out   = (const float*)d_in[20];
    const float* b_out   = (const float*)d_in[21];

    float *ctxp, *xcat, *gatesx, *gates, *hcat, *hbuf, *cbuf, *qb;
    cudaGetSymbolAddress((void**)&ctxp,   g_ctxp);
    cudaGetSymbolAddress((void**)&xcat,   g_xcat);
    cudaGetSymbolAddress((void**)&gatesx, g_gatesx);
    cudaGetSymbolAddress((void**)&gates,  g_gates);
    cudaGetSymbolAddress((void**)&hcat,   g_hcat);
    cudaGetSymbolAddress((void**)&hbuf,   g_hbuf);
    cudaGetSymbolAddress((void**)&cbuf,   g_cbuf);
    cudaGetSymbolAddress((void**)&qb,     g_q);

    cudaFuncSetAttribute(att_kernel, cudaFuncAttributeMaxDynamicSharedMemorySize,
                         ATT_SMEM_FLOATS * (int)sizeof(float));

    float* dout = (float*)d_out;
    const size_t OUT_N  = (size_t)BB * TT * NLAB;   // 1572864
    const size_t PRED_N = (size_t)BB * TT;          // 12288
    float* predp = ((size_t)out_size >= OUT_N + PRED_N) ? (dout + OUT_N) : nullptr;
    float* hfp   = ((size_t)out_size >= OUT_N + PRED_N + 2u * BB * HID) ? (dout + OUT_N + PRED_N) : nullptr;
    float* cfp   = hfp ? (hfp + (size_t)BB * HID) : nullptr;

    // Initial state
    cudaMemcpyAsync(hbuf, h0, (size_t)BB * HID * sizeof(float), cudaMemcpyDeviceToDevice, 0);
    cudaMemcpyAsync(cbuf, c0, (size_t)BB * HID * sizeof(float), cudaMemcpyDeviceToDevice, 0);

    // ctx_proj = context @ W_actx + b_actx    [65536,1024]x[1024,1024]
    {
        dim3 grid(HID / 128, (BB * SS) / 128);
        sgemm_kernel<128, 128, 8, 8, 8, false><<<grid, 256>>>(
            context, HID, W_actx, HID, b_actx, nullptr, 0, ctxp, HID, HID);
    }
    // xcat, then gates_x = xcat @ W_ih + b_ih  [12288,512]x[512,4096]
    {
        int n = BB * TT * 2 * EMB;
        xcat_kernel<<<(n + 255) / 256, 256>>>(decoder_input, cur, lab, emb, xcat);
        dim3 grid((4 * HID) / 128, (BB * TT) / 128);
        sgemm_kernel<128, 128, 8, 8, 8, false><<<grid, 256>>>(
            xcat, 2 * EMB, W_ih, 4 * HID, b_ih, nullptr, 0, gatesx, 4 * HID, 2 * EMB);
    }

    for (int t = 0; t < TT; t++) {
        // gates = gates_x[:,t,:] + h @ W_hh + b_hh   [256,1024]x[1024,4096]
        {
            dim3 grid((4 * HID) / 64, BB / 64);
            sgemm_kernel<64, 64, 16, 4, 4, false><<<grid, 256>>>(
                hbuf, HID, W_hh, 4 * HID, b_hh,
                gatesx + (size_t)t * 4 * HID, TT * 4 * HID,
                gates, 4 * HID, HID);
        }
        // LSTM pointwise -> c, h_lstm
        lstm_kernel<<<(BB * HID) / 256, 256>>>(gates, cbuf, hcat);
        // q = h_lstm @ W_ain + b_ain   [256,1024]x[1024,1024]
        {
            dim3 grid(HID / 64, BB / 64);
            sgemm_kernel<64, 64, 16, 4, 4, false><<<grid, 256>>>(
                hcat + HID, 2 * HID, W_ain, HID, b_ain, nullptr, 0, qb, HID, HID);
        }
        // attention -> weighted into hcat[:, :HID]
        att_kernel<<<BB, ATT_THREADS, ATT_SMEM_FLOATS * sizeof(float)>>>(ctxp, qb, Vw, hcat);
        // hidden_t = tanh([weighted,h_lstm] @ W_ho + b_ho)  [256,2048]x[2048,1024]
        {
            dim3 grid(HID / 64, BB / 64);
            sgemm_kernel<64, 64, 16, 4, 4, true><<<grid, 256>>>(
                hcat, 2 * HID, W_ho, HID, b_ho, nullptr, 0, hbuf, HID, 2 * HID);
        }
        // out + argmax
        out_kernel<<<BB / 4, NLAB>>>(hbuf, hcat, xcat, W_out, b_out, t, dout, predp);
    }

    if (hfp) {
        cudaMemcpyAsync(hfp, hbuf, (size_t)BB * HID * sizeof(float), cudaMemcpyDeviceToDevice, 0);
        cudaMemcpyAsync(cfp, cbuf, (size_t)BB * HID * sizeof(float), cudaMemcpyDeviceToDevice, 0);
    }
}

// round 3
// speedup vs baseline: 1.7791x; 1.7791x over previous
#include <cuda_runtime.h>
#include <cuda_bf16.h>
#include <math.h>

// Problem constants
#define BB   256
#define SS   256
#define TT   48
#define HID  1024
#define EMB  256
#define NLAB 128

// ---------------------------------------------------------------------------
// Scratch (device globals; no allocation allowed)
// ---------------------------------------------------------------------------
__device__ float g_ctxp[(size_t)BB * SS * HID];        // 256 MB
__device__ float g_xcat[(size_t)BB * TT * (2 * EMB)];  // 24 MB
__device__ float g_gatesx[(size_t)BB * TT * 4 * HID];  // 201 MB
__device__ float g_hcat[BB * 2 * HID];                 // [:, :HID]=weighted, [:, HID:]=h_lstm
__device__ float g_hbuf[BB * HID];                     // carried hidden (hidden_t)
__device__ float g_cbuf[BB * HID];                     // carried cell
__device__ float g_q[BB * HID];

// ---------------------------------------------------------------------------
// cp.async helpers
// ---------------------------------------------------------------------------
__device__ __forceinline__ void cpa16(void* dst, const void* src) {
    unsigned d = (unsigned)__cvta_generic_to_shared(dst);
    asm volatile("cp.async.ca.shared.global [%0], [%1], 16;\n" :: "r"(d), "l"(src));
}
__device__ __forceinline__ void cpa_commit() {
    asm volatile("cp.async.commit_group;\n");
}
template<int N>
__device__ __forceinline__ void cpa_wait() {
    asm volatile("cp.async.wait_group %0;\n" :: "n"(N));
}

// ---------------------------------------------------------------------------
// Double-buffered SGEMM: C = A[M,K]*B[K,N] + bias (opt tanh). 256 threads.
// Constraints: (BM/TM)*(BN/TN)==256, BK%4==0, K%BK==0, dims divide tiles.
// A smem kept row-major [BM][BK] (A-operand reads are warp-uniform broadcasts).
// ---------------------------------------------------------------------------
template<int BM, int BN, int BK, int TM, int TN, bool DO_TANH>
__global__ void __launch_bounds__(256)
sgemm_db(const float* __restrict__ A, int lda,
         const float* __restrict__ B, int ldb,
         const float* __restrict__ bias,
         float* __restrict__ C, int ldc, int K)
{
    __shared__ float As[2][BM][BK];
    __shared__ float Bs[2][BK][BN];

    const int tid  = threadIdx.x;
    const int row0 = blockIdx.y * BM;
    const int col0 = blockIdx.x * BN;
    const int tx = tid % (BN / TN);
    const int ty = tid / (BN / TN);

    constexpr int A4 = BM * BK / 4;
    constexpr int B4 = BK * BN / 4;

    auto load_tiles = [&](int k0, int buf) {
        for (int i = tid; i < A4; i += 256) {
            int ar = i / (BK / 4), ac = (i % (BK / 4)) * 4;
            cpa16(&As[buf][ar][ac], A + (size_t)(row0 + ar) * lda + k0 + ac);
        }
        for (int i = tid; i < B4; i += 256) {
            int br = i / (BN / 4), bc = (i % (BN / 4)) * 4;
            cpa16(&Bs[buf][br][bc], B + (size_t)(k0 + br) * ldb + col0 + bc);
        }
    };

    float acc[TM][TN];
#pragma unroll
    for (int i = 0; i < TM; i++)
#pragma unroll
        for (int j = 0; j < TN; j++) acc[i][j] = 0.f;

    const int T = K / BK;
    load_tiles(0, 0);
    cpa_commit();

    for (int t = 0; t < T; t++) {
        if (t + 1 < T) { load_tiles((t + 1) * BK, (t + 1) & 1); cpa_commit(); cpa_wait<1>(); }
        else           { cpa_wait<0>(); }
        __syncthreads();
        const int buf = t & 1;
#pragma unroll
        for (int kk = 0; kk < BK; kk++) {
            float af[TM], bf[TN];
#pragma unroll
            for (int i = 0; i < TM; i++) af[i] = As[buf][ty * TM + i][kk];
#pragma unroll
            for (int j = 0; j < TN; j++) bf[j] = Bs[buf][kk][tx * TN + j];
#pragma unroll
            for (int i = 0; i < TM; i++)
#pragma unroll
                for (int j = 0; j < TN; j++)
                    acc[i][j] = fmaf(af[i], bf[j], acc[i][j]);
        }
        __syncthreads();
    }

#pragma unroll
    for (int i = 0; i < TM; i++) {
        const int r = row0 + ty * TM + i;
#pragma unroll
        for (int j = 0; j < TN; j++) {
            const int c = col0 + tx * TN + j;
            float v = acc[i][j] + bias[c];
            if (DO_TANH) v = tanhf(v);
            C[(size_t)r * ldc + c] = v;
        }
    }
}

// ---------------------------------------------------------------------------
// Fused gates GEMM + LSTM: gates = gates_x[:,t] + h @ W_hh + b_hh, then the
// LSTM pointwise. N-tile is interleaved: block col jc covers j in
// [jc*32, jc*32+32) for ALL FOUR gate chunks; each thread owns one j across
// the 4 gates, so the epilogue computes c_t and h_lstm directly.
// BM=64, BK=16, 256 threads (tx=32 j's, ty=8, TM=8 rows). grid (32, B/64).
// ---------------------------------------------------------------------------
__global__ void __launch_bounds__(256)
gates_lstm_kernel(const float* __restrict__ A,      // h  [B, HID]
                  const float* __restrict__ Whh,    // [HID, 4*HID]
                  const float* __restrict__ bhh,
                  const float* __restrict__ gatesx, // [B, T, 4*HID]
                  int t,
                  float* __restrict__ cbuf,
                  float* __restrict__ hcat)
{
    constexpr int BM = 64, BK = 16;
    __shared__ float As[2][BM][BK];
    __shared__ float Bs[2][BK][128];

    const int tid = threadIdx.x;
    const int tx = tid & 31;          // j within group
    const int ty = tid >> 5;          // row group
    const int jc = blockIdx.x;        // 0..31
    const int b0 = blockIdx.y * BM;

    auto load_tiles = [&](int k0, int buf) {
        {   // A: 64x16 = 256 float4, 1 per thread
            int ar = tid >> 2, ac = (tid & 3) * 4;
            cpa16(&As[buf][ar][ac], A + (size_t)(b0 + ar) * HID + k0 + ac);
        }
        for (int i = tid; i < 512; i += 256) {  // B: 16x128
            int br = i >> 5;
            int bci = (i & 31) * 4;
            int g = bci >> 5, jj = bci & 31;
            cpa16(&Bs[buf][br][bci],
                  Whh + (size_t)(k0 + br) * (4 * HID) + g * HID + jc * 32 + jj);
        }
    };

    float acc[8][4];
#pragma unroll
    for (int i = 0; i < 8; i++)
#pragma unroll
        for (int g = 0; g < 4; g++) acc[i][g] = 0.f;

    const int T = HID / BK;
    load_tiles(0, 0);
    cpa_commit();
    for (int kt = 0; kt < T; kt++) {
        if (kt + 1 < T) { load_tiles((kt + 1) * BK, (kt + 1) & 1); cpa_commit(); cpa_wait<1>(); }
        else            { cpa_wait<0>(); }
        __syncthreads();
        const int buf = kt & 1;
#pragma unroll
        for (int kk = 0; kk < BK; kk++) {
            float af[8], bf[4];
#pragma unroll
            for (int i = 0; i < 8; i++) af[i] = As[buf][ty * 8 + i][kk];
#pragma unroll
            for (int g = 0; g < 4; g++) bf[g] = Bs[buf][kk][g * 32 + tx];
#pragma unroll
            for (int i = 0; i < 8; i++)
#pragma unroll
                for (int g = 0; g < 4; g++)
                    acc[i][g] = fmaf(af[i], bf[g], acc[i][g]);
        }
        __syncthreads();
    }

    const int j = jc * 32 + tx;
#pragma unroll
    for (int i = 0; i < 8; i++) {
        const int b = b0 + ty * 8 + i;
        const float* gx = gatesx + ((size_t)b * TT + t) * (4 * HID);
        float gi = acc[i][0] + bhh[j]            + gx[j];
        float gf = acc[i][1] + bhh[HID + j]      + gx[HID + j];
        float gg = acc[i][2] + bhh[2 * HID + j]  + gx[2 * HID + j];
        float go = acc[i][3] + bhh[3 * HID + j]  + gx[3 * HID + j];
        float si = 1.f / (1.f + expf(-gi));
        float sf = 1.f / (1.f + expf(-gf));
        float so = 1.f / (1.f + expf(-go));
        float cn = sf * cbuf[(size_t)b * HID + j] + si * tanhf(gg);
        cbuf[(size_t)b * HID + j] = cn;
        hcat[(size_t)b * 2 * HID + HID + j] = so * tanhf(cn);
    }
}

// ---------------------------------------------------------------------------
// xcat builder
// ---------------------------------------------------------------------------
__global__ void xcat_kernel(const float* __restrict__ dec,
                            const int* __restrict__ cur,
                            const int* __restrict__ lab,
                            const float* __restrict__ emb,
                            float* __restrict__ xcat)
{
    int idx = blockIdx.x * blockDim.x + threadIdx.x;
    if (idx >= BB * TT * 2 * EMB) return;
    int k  = idx & (2 * EMB - 1);
    int bt = idx >> 9;
    int t  = bt % TT;
    int b  = bt / TT;
    float v;
    if (k < EMB) {
        if (t == 0) v = dec[b * EMB + k];
        else        v = emb[cur[b * TT + (t - 1)] * EMB + k];
    } else {
        v = emb[lab[b * TT + t] * EMB + (k - EMB)];
    }
    xcat[idx] = v;
}

// ---------------------------------------------------------------------------
// Fused Bahdanau attention with online softmax (single pass over ctx_proj).
// ---------------------------------------------------------------------------
#define ATT_THREADS 512
#define ATT_CHUNK   16
#define ATT_SMEM_FLOATS (ATT_CHUNK * HID + HID + HID + ATT_CHUNK + ATT_CHUNK)

__global__ void __launch_bounds__(ATT_THREADS, 1)
att_kernel(const float* __restrict__ ctxp,
           const float* __restrict__ q,
           const float* __restrict__ Vw,
           float* __restrict__ hcat)
{
    extern __shared__ float sm[];
    float* chunk = sm;                       // 16*1024
    float* qs    = sm + ATT_CHUNK * HID;     // 1024
    float* Vs    = qs + HID;                 // 1024
    float* e_sm  = Vs + HID;                 // 16
    float* p_sm  = e_sm + ATT_CHUNK;         // 16

    const int b = blockIdx.x, tid = threadIdx.x;
    const int warp = tid >> 5, lane = tid & 31;

    for (int i = tid; i < HID; i += ATT_THREADS) {
        qs[i] = q[(size_t)b * HID + i];
        Vs[i] = Vw[i];
    }

    float m = -INFINITY, l = 0.f, acc0 = 0.f, acc1 = 0.f;
    const float* base = ctxp + (size_t)b * SS * HID;

    for (int s0 = 0; s0 < SS; s0 += ATT_CHUNK) {
        __syncthreads();
        const float4* src  = (const float4*)(base + (size_t)s0 * HID);
        float4*       dst4 = (float4*)chunk;
#pragma unroll
        for (int i = tid; i < ATT_CHUNK * HID / 4; i += ATT_THREADS) dst4[i] = src[i];
        __syncthreads();

        {
            const float* row = chunk + warp * HID;
            float sum = 0.f;
#pragma unroll 8
            for (int i = lane; i < HID; i += 32)
                sum += tanhf(qs[i] + row[i]) * Vs[i];
#pragma unroll
            for (int off = 16; off; off >>= 1)
                sum += __shfl_xor_sync(0xffffffffu, sum, off);
            if (lane == 0) e_sm[warp] = sum;
        }
        __syncthreads();

        float mc = m;
#pragma unroll
        for (int s = 0; s < ATT_CHUNK; s++) mc = fmaxf(mc, e_sm[s]);
        float scale = expf(m - mc);
        if (tid < ATT_CHUNK) p_sm[tid] = expf(e_sm[tid] - mc);
        __syncthreads();

        float psum = 0.f, a0 = 0.f, a1 = 0.f;
#pragma unroll
        for (int s = 0; s < ATT_CHUNK; s++) {
            float p = p_sm[s];
            psum += p;
            a0 = fmaf(p, chunk[s * HID + tid], a0);
            a1 = fmaf(p, chunk[s * HID + tid + ATT_THREADS], a1);
        }
        l    = l * scale + psum;
        acc0 = acc0 * scale + a0;
        acc1 = acc1 * scale + a1;
        m    = mc;
    }

    float inv = 1.f / l;
    hcat[(size_t)b * 2 * HID + tid]               = acc0 * inv;
    hcat[(size_t)b * 2 * HID + tid + ATT_THREADS] = acc1 * inv;
}

// ---------------------------------------------------------------------------
// out = [hidden_t, weighted, x_t] @ W_out + b_out  (K=2304, N=128) + argmax.
// 512 threads: col = tid%128, 4-way K-split = tid/128.  2 batch rows/block.
// ---------------------------------------------------------------------------
#define OUT_K (2 * HID + EMB)
#define OUT_KS (OUT_K / 4)   // 576
__global__ void __launch_bounds__(512)
out_kernel(const float* __restrict__ hbuf,
           const float* __restrict__ hcat,
           const float* __restrict__ xcat,
           const float* __restrict__ Wout,
           const float* __restrict__ bout,
           int t,
           float* __restrict__ outp,
           float* __restrict__ predp)
{
    __shared__ float arow[2][OUT_K];
    __shared__ float red[4][2][NLAB];
    __shared__ float sv[2][NLAB];
    __shared__ int   si[2][NLAB];

    const int tid = threadIdx.x;
    const int col = tid & 127;
    const int ks  = tid >> 7;
    const int b0  = blockIdx.x * 2;

    for (int idx = tid; idx < 2 * OUT_K; idx += 512) {
        int r = idx / OUT_K, k = idx % OUT_K;
        int b = b0 + r;
        float v;
        if (k < HID)            v = hbuf[(size_t)b * HID + k];
        else if (k < 2 * HID)   v = hcat[(size_t)b * 2 * HID + (k - HID)];
        else                    v = xcat[((size_t)b * TT + t) * (2 * EMB) + (k - 2 * HID)];
        arow[r][k] = v;
    }
    __syncthreads();

    float a0 = 0.f, a1 = 0.f;
    const int kbeg = ks * OUT_KS;
#pragma unroll 8
    for (int k = kbeg; k < kbeg + OUT_KS; k++) {
        float w = Wout[(size_t)k * NLAB + col];
        a0 = fmaf(arow[0][k], w, a0);
        a1 = fmaf(arow[1][k], w, a1);
    }
    red[ks][0][col] = a0;
    red[ks][1][col] = a1;
    __syncthreads();

    if (tid < 256) {
        int r = tid >> 7;
        float v = red[0][r][col] + red[1][r][col] + red[2][r][col] + red[3][r][col] + bout[col];
        outp[((size_t)(b0 + r) * TT + t) * NLAB + col] = v;
        sv[r][col] = v;
        si[r][col] = col;
    }
    if (!predp) return;
    __syncthreads();
    for (int off = NLAB / 2; off; off >>= 1) {
        if (tid < 256) {
            int r = tid >> 7;
            if (col < off) {
                float ov = sv[r][col + off]; int oi = si[r][col + off];
                if (ov > sv[r][col] || (ov == sv[r][col] && oi < si[r][col])) {
                    sv[r][col] = ov; si[r][col] = oi;
                }
            }
        }
        __syncthreads();
    }
    if (tid < 2) predp[(size_t)(b0 + tid) * TT + t] = (float)si[tid][0];
}

// ---------------------------------------------------------------------------
// Launch
// ---------------------------------------------------------------------------
extern "C" void kernel_launch(void* const* d_in, const int* in_sizes, int n_in,
                              void* d_out, int out_size)
{
    (void)in_sizes; (void)n_in;
    const float* decoder_input = (const float*)d_in[2];
    const float* h0      = (const float*)d_in[3];
    const float* c0      = (const float*)d_in[4];
    const float* context = (const float*)d_in[5];
    const int*   cur     = (const int*)d_in[6];
    const int*   lab     = (const int*)d_in[7];
    const float* emb     = (const float*)d_in[8];
    const float* W_ih    = (const float*)d_in[9];
    const float* b_ih    = (const float*)d_in[10];
    const float* W_hh    = (const float*)d_in[11];
    const float* b_hh    = (const float*)d_in[12];
    const float* W_ho    = (const float*)d_in[13];
    const float* b_ho    = (const float*)d_in[14];
    const float* W_ain   = (const float*)d_in[15];
    const float* b_ain   = (const float*)d_in[16];
    const float* W_actx  = (const float*)d_in[17];
    const float* b_actx  = (const float*)d_in[18];
    const float* Vw      = (const float*)d_in[19];
    const float* W_out   = (const float*)d_in[20];
    const float* b_out   = (const float*)d_in[21];

    float *ctxp, *xcat, *gatesx, *hcat, *hbuf, *cbuf, *qb;
    cudaGetSymbolAddress((void**)&ctxp,   g_ctxp);
    cudaGetSymbolAddress((void**)&xcat,   g_xcat);
    cudaGetSymbolAddress((void**)&gatesx, g_gatesx);
    cudaGetSymbolAddress((void**)&hcat,   g_hcat);
    cudaGetSymbolAddress((void**)&hbuf,   g_hbuf);
    cudaGetSymbolAddress((void**)&cbuf,   g_cbuf);
    cudaGetSymbolAddress((void**)&qb,     g_q);

    cudaFuncSetAttribute(att_kernel, cudaFuncAttributeMaxDynamicSharedMemorySize,
                         ATT_SMEM_FLOATS * (int)sizeof(float));

    float* dout = (float*)d_out;
    const size_t OUT_N  = (size_t)BB * TT * NLAB;
    const size_t PRED_N = (size_t)BB * TT;
    float* predp = ((size_t)out_size >= OUT_N + PRED_N) ? (dout + OUT_N) : nullptr;
    float* hfp   = ((size_t)out_size >= OUT_N + PRED_N + 2u * BB * HID) ? (dout + OUT_N + PRED_N) : nullptr;
    float* cfp   = hfp ? (hfp + (size_t)BB * HID) : nullptr;

    cudaMemcpyAsync(hbuf, h0, (size_t)BB * HID * sizeof(float), cudaMemcpyDeviceToDevice, 0);
    cudaMemcpyAsync(cbuf, c0, (size_t)BB * HID * sizeof(float), cudaMemcpyDeviceToDevice, 0);

    // ctx_proj = context @ W_actx + b_actx   [65536,1024]x[1024,1024]
    {
        dim3 grid(HID / 128, (BB * SS) / 128);
        sgemm_db<128, 128, 16, 8, 8, false><<<grid, 256>>>(
            context, HID, W_actx, HID, b_actx, ctxp, HID, HID);
    }
    // xcat, then gates_x = xcat @ W_ih + b_ih  [12288,512]x[512,4096]
    {
        int n = BB * TT * 2 * EMB;
        xcat_kernel<<<(n + 255) / 256, 256>>>(decoder_input, cur, lab, emb, xcat);
        dim3 grid((4 * HID) / 128, (BB * TT) / 128);
        sgemm_db<128, 128, 16, 8, 8, false><<<grid, 256>>>(
            xcat, 2 * EMB, W_ih, 4 * HID, b_ih, gatesx, 4 * HID, 2 * EMB);
    }

    for (int t = 0; t < TT; t++) {
        // gates GEMM + LSTM fused
        {
            dim3 grid(32, BB / 64);
            gates_lstm_kernel<<<grid, 256>>>(hbuf, W_hh, b_hh, gatesx, t, cbuf, hcat);
        }
        // q = h_lstm @ W_ain + b_ain   [256,1024]x[1024,1024]
        {
            dim3 grid(HID / 64, BB / 32);
            sgemm_db<32, 64, 16, 4, 2, false><<<grid, 256>>>(
                hcat + HID, 2 * HID, W_ain, HID, b_ain, qb, HID, HID);
        }
        // attention -> weighted into hcat[:, :HID]
        att_kernel<<<BB, ATT_THREADS, ATT_SMEM_FLOATS * sizeof(float)>>>(ctxp, qb, Vw, hcat);
        // hidden_t = tanh([weighted,h_lstm] @ W_ho + b_ho)  [256,2048]x[2048,1024]
        {
            dim3 grid(HID / 64, BB / 32);
            sgemm_db<32, 64, 16, 4, 2, true><<<grid, 256>>>(
                hcat, 2 * HID, W_ho, HID, b_ho, hbuf, HID, 2 * HID);
        }
        // out + argmax
        out_kernel<<<BB / 2, 512>>>(hbuf, hcat, xcat, W_out, b_out, t, dout, predp);
    }

    if (hfp) {
        cudaMemcpyAsync(hfp, hbuf, (size_t)BB * HID * sizeof(float), cudaMemcpyDeviceToDevice, 0);
        cudaMemcpyAsync(cfp, cbuf, (size_t)BB * HID * sizeof(float), cudaMemcpyDeviceToDevice, 0);
    }
}